// round 14
// baseline (speedup 1.0000x reference)
#include <cuda_runtime.h>
#include <math.h>
#include <stdint.h>

#define BB 8
#define CH 64
#define HH 128
#define WW 128

typedef unsigned long long u64;

// ---------------- scratch (device globals; no allocation allowed) ----------
__device__ float g_x_nhwc[BB*HH*WW*CH];   // x transposed to NHWC
__device__ float g_xh_nhwc[BB*HH*WW*CH];  // horizontal-pass output, NHWC
__device__ float g_omh[BB*HH*WW*12];      // dy0,dx0,dy1,dx1,dy2,dx2,m0,m1,m2,pad
__device__ float g_omv[BB*HH*WW*12];
// Packed weight images: [pass][k][c][64 floats]; row = 32 u64 out-pairs:
// u64 pos = i2*16 + og*2 + t holds (w[2jg], w[2jg+1]), jg = og*4 + i2*2 + t
__device__ __align__(16) float g_wB[2][12288];

// ---------------- f32x2 packed helpers (Blackwell FFMA2) -------------------
static __device__ __forceinline__ u64 pk2(float a, float b) {
    u64 r; asm("mov.b64 %0, {%1,%2};" : "=l"(r) : "f"(a), "f"(b)); return r;
}
static __device__ __forceinline__ void upk2(u64 v, float &a, float &b) {
    asm("mov.b64 {%0,%1}, %2;" : "=f"(a), "=f"(b) : "l"(v));
}
static __device__ __forceinline__ u64 ffma2(u64 a, u64 b, u64 c) {
    u64 d; asm("fma.rn.f32x2 %0, %1, %2, %3;" : "=l"(d) : "l"(a), "l"(b), "l"(c)); return d;
}
static __device__ __forceinline__ u64 fmul2(u64 a, u64 b) {
    u64 d; asm("mul.rn.f32x2 %0, %1, %2;" : "=l"(d) : "l"(a), "l"(b)); return d;
}
static __device__ __forceinline__ float f4c(const float4 &v, int i) {
    return i == 0 ? v.x : (i == 1 ? v.y : (i == 2 ? v.z : v.w));
}

// ---------------- K-1: weight repack (runs once, tiny) ---------------------
__global__ __launch_bounds__(256) void prep_weights(
    const float* __restrict__ wh, const float* __restrict__ wv)
{
    int i = blockIdx.x*256 + threadIdx.x;
    if (i >= 24576) return;
    int pass = i / 12288;
    int r = i % 12288;
    int k = r / 4096;
    int rr = r % 4096;
    int c = rr / 64;
    int f = rr % 64;
    int pos = f >> 1, e = f & 1;
    int i2 = pos >> 4, og = (pos >> 1) & 7, t = pos & 1;
    int jg = og*4 + i2*2 + t;
    int o = 2*jg + e;
    const float* w = pass ? wv : wh;
    g_wB[pass][r] = w[o*192 + c*3 + k];
}

// ---------------- K0: NCHW -> NHWC transpose -------------------------------
__global__ __launch_bounds__(256) void transpose_kernel(const float* __restrict__ in) {
    __shared__ float tile[CH][33];
    int n = blockIdx.z, y = blockIdx.y, x0 = blockIdx.x * 32;
    int tx = threadIdx.x, ty = threadIdx.y;
    #pragma unroll
    for (int c = ty; c < CH; c += 8)
        tile[c][tx] = in[(((size_t)n*CH + c)*HH + y)*WW + x0 + tx];
    __syncthreads();
    int t = ty*32 + tx;
    #pragma unroll
    for (int i = 0; i < 8; i++) {
        int idx = t + i*256;
        int px = idx >> 6, c = idx & 63;
        g_x_nhwc[(((size_t)n*HH + y)*WW + x0 + px)*CH + c] = tile[c][px];
    }
}

// ---------------- K1: offsets + masks, 2 px (adjacent rows)/thread ---------
__global__ __launch_bounds__(256, 2) void offmask_kernel(
    const float* __restrict__ woh, const float* __restrict__ boh,
    const float* __restrict__ wmh, const float* __restrict__ bmh,
    const float* __restrict__ wov, const float* __restrict__ bov,
    const float* __restrict__ wmv, const float* __restrict__ bmv)
{
    __shared__ float ws[64*6*12];
    int tid = threadIdx.x;
    for (int i = tid; i < 64*6*12; i += 256) {
        int o = i % 12, j = (i/12) % 6, c = i/72;
        float v = 0.f;
        if (o < 6)      v = (j < 3) ? woh[o*192 + c*3 + j] : wov[o*192 + c*3 + (j-3)];
        else if (o < 9) v = (j < 3) ? wmh[(o-6)*192 + c*3 + j] : wmv[(o-6)*192 + c*3 + (j-3)];
        ws[i] = v;
    }
    __syncthreads();

    int x = tid & 127;
    int pairidx = blockIdx.x*2 + (tid >> 7);
    int row0 = pairidx*2;
    int y = row0 & 127;
    size_t p0 = (size_t)row0*WW + x;
    size_t p1 = p0 + WW;

    u64 H0a=0,H0b=0,H0c=0,H0d=0, V0a=0,V0b=0,V0c=0,V0d=0;
    u64 H1a=0,H1b=0,H1c=0,H1d=0, V1a=0,V1b=0,V1c=0,V1d=0;
    float H0e=0.f, V0e=0.f, H1e=0.f, V1e=0.f;

    const float* pc0 = g_x_nhwc + p0*CH;
    const float* pc1 = g_x_nhwc + p1*CH;
    bool hl = x > 0, hr = x < WW-1;
    bool vu = y > 0, vd = (y + 2) < HH;
    const float* pl0 = pc0 - CH;
    const float* pr0 = pc0 + CH;
    const float* pl1 = pc1 - CH;
    const float* pr1 = pc1 + CH;
    const float* pu  = pc0 - (size_t)WW*CH;
    const float* pd  = pc1 + (size_t)WW*CH;
    const float4 Z = make_float4(0.f,0.f,0.f,0.f);

    for (int c4 = 0; c4 < 16; c4++) {
        float4 fc0 = *(const float4*)(pc0 + c4*4);
        float4 fc1 = *(const float4*)(pc1 + c4*4);
        float4 fl0 = hl ? *(const float4*)(pl0 + c4*4) : Z;
        float4 fr0 = hr ? *(const float4*)(pr0 + c4*4) : Z;
        float4 fl1 = hl ? *(const float4*)(pl1 + c4*4) : Z;
        float4 fr1 = hr ? *(const float4*)(pr1 + c4*4) : Z;
        float4 fu  = vu ? *(const float4*)(pu  + c4*4) : Z;
        float4 fd  = vd ? *(const float4*)(pd  + c4*4) : Z;
        #pragma unroll
        for (int cc = 0; cc < 4; cc++) {
            int c = c4*4 + cc;
            float h0[3] = { f4c(fl0,cc), f4c(fc0,cc), f4c(fr0,cc) };
            float h1[3] = { f4c(fl1,cc), f4c(fc1,cc), f4c(fr1,cc) };
            float v0[3] = { f4c(fu,cc),  f4c(fc0,cc), f4c(fc1,cc) };
            float v1[3] = { f4c(fc0,cc), f4c(fc1,cc), f4c(fd,cc)  };
            #pragma unroll
            for (int j = 0; j < 3; j++) {
                const float* wb = &ws[(c*6 + j)*12];
                ulonglong2 W0 = *(const ulonglong2*)(wb);
                ulonglong2 W1 = *(const ulonglong2*)(wb + 4);
                float w8 = wb[8];
                u64 s0 = pk2(h0[j], h0[j]);
                H0a = ffma2(s0, W0.x, H0a); H0b = ffma2(s0, W0.y, H0b);
                H0c = ffma2(s0, W1.x, H0c); H0d = ffma2(s0, W1.y, H0d);
                H0e = fmaf(h0[j], w8, H0e);
                u64 s1 = pk2(h1[j], h1[j]);
                H1a = ffma2(s1, W0.x, H1a); H1b = ffma2(s1, W0.y, H1b);
                H1c = ffma2(s1, W1.x, H1c); H1d = ffma2(s1, W1.y, H1d);
                H1e = fmaf(h1[j], w8, H1e);

                const float* ub = &ws[(c*6 + j + 3)*12];
                ulonglong2 U0 = *(const ulonglong2*)(ub);
                ulonglong2 U1 = *(const ulonglong2*)(ub + 4);
                float u8 = ub[8];
                u64 t0 = pk2(v0[j], v0[j]);
                V0a = ffma2(t0, U0.x, V0a); V0b = ffma2(t0, U0.y, V0b);
                V0c = ffma2(t0, U1.x, V0c); V0d = ffma2(t0, U1.y, V0d);
                V0e = fmaf(v0[j], u8, V0e);
                u64 t1 = pk2(v1[j], v1[j]);
                V1a = ffma2(t1, U0.x, V1a); V1b = ffma2(t1, U0.y, V1b);
                V1c = ffma2(t1, U1.x, V1c); V1d = ffma2(t1, U1.y, V1d);
                V1e = fmaf(v1[j], u8, V1e);
            }
        }
    }

    float b0 = __ldg(boh+0), b1 = __ldg(boh+1), b2 = __ldg(boh+2);
    float b3 = __ldg(boh+3), b4 = __ldg(boh+4), b5 = __ldg(boh+5);
    float c0 = __ldg(bov+0), c1 = __ldg(bov+1), c2 = __ldg(bov+2);
    float c3 = __ldg(bov+3), c4b = __ldg(bov+4), c5 = __ldg(bov+5);
    float mb0 = __ldg(bmh+0), mb1 = __ldg(bmh+1), mb2 = __ldg(bmh+2);
    float nb0 = __ldg(bmv+0), nb1 = __ldg(bmv+1), nb2 = __ldg(bmv+2);

    #pragma unroll
    for (int r = 0; r < 2; r++) {
        float A[9], V[9];
        if (r == 0) {
            upk2(H0a,A[0],A[1]); upk2(H0b,A[2],A[3]); upk2(H0c,A[4],A[5]);
            upk2(H0d,A[6],A[7]); A[8]=H0e;
            upk2(V0a,V[0],V[1]); upk2(V0b,V[2],V[3]); upk2(V0c,V[4],V[5]);
            upk2(V0d,V[6],V[7]); V[8]=V0e;
        } else {
            upk2(H1a,A[0],A[1]); upk2(H1b,A[2],A[3]); upk2(H1c,A[4],A[5]);
            upk2(H1d,A[6],A[7]); A[8]=H1e;
            upk2(V1a,V[0],V[1]); upk2(V1b,V[2],V[3]); upk2(V1c,V[4],V[5]);
            upk2(V1d,V[6],V[7]); V[8]=V1e;
        }
        size_t p = r ? p1 : p0;
        float mh0 = 1.f/(1.f + expf(-(A[6] + mb0)));
        float mh1 = 1.f/(1.f + expf(-(A[7] + mb1)));
        float mh2 = 1.f/(1.f + expf(-(A[8] + mb2)));
        float mv0 = 1.f/(1.f + expf(-(V[6] + nb0)));
        float mv1 = 1.f/(1.f + expf(-(V[7] + nb1)));
        float mv2 = 1.f/(1.f + expf(-(V[8] + nb2)));
        float* oh = g_omh + p*12;
        *(float4*)(oh+0) = make_float4(A[0]+b0, A[1]+b1, A[2]+b2, A[3]+b3);
        *(float4*)(oh+4) = make_float4(A[4]+b4, A[5]+b5, mh0, mh1);
        oh[8] = mh2;
        float* ov = g_omv + p*12;
        *(float4*)(ov+0) = make_float4(V[0]+c0, V[1]+c1, V[2]+c2, V[3]+c3);
        *(float4*)(ov+4) = make_float4(V[4]+c4b, V[5]+c5, mv0, mv1);
        ov[8] = mv2;
    }
}

// ---------------- K2/K3: deformable axial pass (warp-spec, B via LDG) ------
// Block = 192 thr: threads 0-63 = producers (gather), 64-191 = consumers
// (GEMM, 8 px x 8 outs each). A double-buffered in smem; B weights read
// directly from global (L1-resident, coalesced 128B rows).
// smem = 18304 floats = 73216 B -> 3 CTAs/SM, regs capped at 112.
#define SMF_A0  0
#define SMF_A1  8192
#define SMF_CW  16384
#define SMF_CB  17920
#define SMF_TOT 18304

template<int VERT, int OUT_NCHW>
__global__ __launch_bounds__(192, 3) void pass_kernel(
    const float* __restrict__ src,   // NHWC input
    const float* __restrict__ om,    // stride-12 offset/mask records
    const float* __restrict__ wB,    // packed weights [3][64][64] (global)
    const float* __restrict__ bias,
    float* __restrict__ dst)
{
    extern __shared__ float smem[];
    float* Abuf[2] = { smem + SMF_A0, smem + SMF_A1 };
    float* cww  = smem + SMF_CW;
    int*  cbase = (int*)(smem + SMF_CB);

    int tid = threadIdx.x;
    int row = blockIdx.x;            // n*H + y
    int n = row >> 7, y = row & 127;
    bool producer = tid < 64;

    // ---- prologue: corner weights/offsets (2 items per thread) ------------
    for (int t = tid; t < 384; t += 192) {
        int k = t / 128, xp = t & 127;
        const float* omb = om + ((size_t)row*WW + xp)*12;
        float dyk = omb[2*k], dxk = omb[2*k + 1], mkk = omb[6 + k];
        float py = (float)y + dyk + (VERT ? (float)(k-1) : 0.f);
        float pxf = (float)xp + dxk + (VERT ? 0.f : (float)(k-1));
        float y0f = floorf(py), x0f = floorf(pxf);
        float wy = py - y0f, wx = pxf - x0f;
        int iy0 = (int)y0f, ix0 = (int)x0f;
        int iy1 = iy0 + 1,  ix1 = ix0 + 1;
        float vy0 = (iy0 >= 0 && iy0 < HH) ? 1.f : 0.f;
        float vy1 = (iy1 >= 0 && iy1 < HH) ? 1.f : 0.f;
        float vx0 = (ix0 >= 0 && ix0 < WW) ? 1.f : 0.f;
        float vx1 = (ix1 >= 0 && ix1 < WW) ? 1.f : 0.f;
        float* cw = &cww[(k*128 + xp)*4];
        cw[0] = (1.f-wy)*(1.f-wx)*vy0*vx0*mkk;
        cw[1] = (1.f-wy)*wx      *vy0*vx1*mkk;
        cw[2] = wy*(1.f-wx)      *vy1*vx0*mkk;
        cw[3] = wy*wx            *vy1*vx1*mkk;
        int cy0 = min(max(iy0,0),HH-1), cy1 = min(max(iy1,0),HH-1);
        int cx0 = min(max(ix0,0),WW-1), cx1 = min(max(ix1,0),WW-1);
        int b00 = ((n*HH + cy0)*WW + cx0)*CH;     // fits in 23 bits
        int fx = cx1 - cx0;
        int fy = cy1 - cy0;
        cbase[k*128 + xp] = b00 | (fx << 24) | (fy << 25);
    }
    __syncthreads();

    // producer roles (64 threads, 2 warps)
    int wid = tid >> 5, lane = tid & 31;
    int p8 = lane >> 3, c8l = lane & 7;
    // consumer roles (128 threads): tile 8 px x 8 outs
    int ctid = tid - 64;
    int og = ctid & 7, pgr = ctid >> 3;   // pgr 0..15

    u64 acc[8][4];
    #pragma unroll
    for (int i = 0; i < 8; i++)
        #pragma unroll
        for (int j = 0; j < 4; j++) acc[i][j] = 0ull;

    // producers: gather tap 0 -> A0 (32 (px,c4g) units per thread)
    if (producer) {
        #pragma unroll
        for (int i = 0; i < 16; i++) {
            int pxg = i*2 + wid;
            int px = pxg*4 + p8;
            const float* cw = &cww[px*4];
            int cv = cbase[px];
            u64 w00p = pk2(cw[0], cw[0]);
            u64 w01p = pk2(cw[1], cw[1]);
            u64 w10p = pk2(cw[2], cw[2]);
            u64 w11p = pk2(cw[3], cw[3]);
            int b00 = cv & 0x00FFFFFF;
            int dx = ((cv >> 24) & 1) << 6;
            int dy = ((cv >> 25) & 1) << 13;
            int b01 = b00 + dx, b10 = b00 + dy, b11 = b10 + dx;
            #pragma unroll
            for (int h = 0; h < 2; h++) {
                int c4g = h*8 + c8l;
                int co = c4g*4;
                ulonglong2 q00 = *(const ulonglong2*)(src + b00 + co);
                ulonglong2 q01 = *(const ulonglong2*)(src + b01 + co);
                ulonglong2 q10 = *(const ulonglong2*)(src + b10 + co);
                ulonglong2 q11 = *(const ulonglong2*)(src + b11 + co);
                u64 r01 = ffma2(w00p, q00.x, ffma2(w01p, q01.x,
                          ffma2(w10p, q10.x, fmul2(w11p, q11.x))));
                u64 r23 = ffma2(w00p, q00.y, ffma2(w01p, q01.y,
                          ffma2(w10p, q10.y, fmul2(w11p, q11.y))));
                float r0, r1, r2, r3;
                upk2(r01, r0, r1); upk2(r23, r2, r3);
                int base = ((pxg ^ (c4g & 7)) << 2) + p8;
                float* ar = Abuf[0] + co*128 + base;
                ar[0*128] = r0; ar[1*128] = r1;
                ar[2*128] = r2; ar[3*128] = r3;
            }
        }
    }
    __syncthreads();

    // ---- pipelined taps: producers fill (k+1) while consumers GEMM (k) ----
    #pragma unroll
    for (int k = 0; k < 3; k++) {
        if (producer) {
            if (k < 2) {
                int kg = k + 1;
                float* Adst = Abuf[kg & 1];
                #pragma unroll
                for (int i = 0; i < 16; i++) {
                    int pxg = i*2 + wid;
                    int px = pxg*4 + p8;
                    const float* cw = &cww[(kg*128 + px)*4];
                    int cv = cbase[kg*128 + px];
                    u64 w00p = pk2(cw[0], cw[0]);
                    u64 w01p = pk2(cw[1], cw[1]);
                    u64 w10p = pk2(cw[2], cw[2]);
                    u64 w11p = pk2(cw[3], cw[3]);
                    int b00 = cv & 0x00FFFFFF;
                    int dx = ((cv >> 24) & 1) << 6;
                    int dy = ((cv >> 25) & 1) << 13;
                    int b01 = b00 + dx, b10 = b00 + dy, b11 = b10 + dx;
                    #pragma unroll
                    for (int h = 0; h < 2; h++) {
                        int c4g = h*8 + c8l;
                        int co = c4g*4;
                        ulonglong2 q00 = *(const ulonglong2*)(src + b00 + co);
                        ulonglong2 q01 = *(const ulonglong2*)(src + b01 + co);
                        ulonglong2 q10 = *(const ulonglong2*)(src + b10 + co);
                        ulonglong2 q11 = *(const ulonglong2*)(src + b11 + co);
                        u64 r01 = ffma2(w00p, q00.x, ffma2(w01p, q01.x,
                                  ffma2(w10p, q10.x, fmul2(w11p, q11.x))));
                        u64 r23 = ffma2(w00p, q00.y, ffma2(w01p, q01.y,
                                  ffma2(w10p, q10.y, fmul2(w11p, q11.y))));
                        float r0, r1, r2, r3;
                        upk2(r01, r0, r1); upk2(r23, r2, r3);
                        int base = ((pxg ^ (c4g & 7)) << 2) + p8;
                        float* ar = Adst + co*128 + base;
                        ar[0*128] = r0; ar[1*128] = r1;
                        ar[2*128] = r2; ar[3*128] = r3;
                    }
                }
            }
        } else {
            // consumers: GEMM tap k; B streamed from global (L1-hit)
            const float* As = Abuf[k & 1];
            const float* bk = wB + k*4096 + og*4;
            #pragma unroll 4
            for (int c = 0; c < 64; c++) {
                int s = (c >> 2) & 7;
                const float* arow = As + c*128;
                float4 a0 = *(const float4*)(arow + (((2*pgr)     ^ s) << 2));
                float4 a1 = *(const float4*)(arow + (((2*pgr + 1) ^ s) << 2));
                const float* brow = bk + c*64;
                ulonglong2 bp0 = __ldg((const ulonglong2*)(brow));       // outs 0-3
                ulonglong2 bp1 = __ldg((const ulonglong2*)(brow + 32));  // outs 4-7
                u64 W0 = bp0.x, W1 = bp0.y, W2 = bp1.x, W3 = bp1.y;
                #pragma unroll
                for (int i = 0; i < 8; i++) {
                    float av = (i < 4) ? f4c(a0, i) : f4c(a1, i - 4);
                    u64 ad = pk2(av, av);
                    acc[i][0] = ffma2(ad, W0, acc[i][0]);
                    acc[i][1] = ffma2(ad, W1, acc[i][1]);
                    acc[i][2] = ffma2(ad, W2, acc[i][2]);
                    acc[i][3] = ffma2(ad, W3, acc[i][3]);
                }
            }
        }
        __syncthreads();
    }

    // ---- epilogue: consumers add bias + store -----------------------------
    if (!producer) {
        float bv[8];
        #pragma unroll
        for (int m = 0; m < 8; m++) bv[m] = __ldg(bias + og*8 + m);

        if (OUT_NCHW) {
            #pragma unroll
            for (int m = 0; m < 8; m++) {
                int j = m >> 1, t = m & 1;
                float v[8];
                #pragma unroll
                for (int i = 0; i < 8; i++) {
                    float lo, hi; upk2(acc[i][j], lo, hi);
                    v[i] = (t ? hi : lo) + bv[m];
                }
                float* db = dst + (((size_t)(n*CH + og*8 + m))*HH + y)*WW + pgr*8;
                *(float4*)(db)     = make_float4(v[0], v[1], v[2], v[3]);
                *(float4*)(db + 4) = make_float4(v[4], v[5], v[6], v[7]);
            }
        } else {
            #pragma unroll
            for (int i = 0; i < 8; i++) {
                int px = pgr*8 + i;
                float s[8];
                #pragma unroll
                for (int j = 0; j < 4; j++) {
                    float lo, hi; upk2(acc[i][j], lo, hi);
                    s[2*j]   = lo + bv[2*j];
                    s[2*j+1] = hi + bv[2*j+1];
                }
                float* db = dst + ((size_t)row*WW + px)*CH + og*8;
                *(float4*)(db)     = make_float4(s[0], s[1], s[2], s[3]);
                *(float4*)(db + 4) = make_float4(s[4], s[5], s[6], s[7]);
            }
        }
    }
}

// ---------------- launch ---------------------------------------------------
extern "C" void kernel_launch(void* const* d_in, const int* in_sizes, int n_in,
                              void* d_out, int out_size) {
    const float* x        = (const float*)d_in[0];
    const float* w_off_h  = (const float*)d_in[1];
    const float* b_off_h  = (const float*)d_in[2];
    const float* w_mask_h = (const float*)d_in[3];
    const float* b_mask_h = (const float*)d_in[4];
    const float* w_off_v  = (const float*)d_in[5];
    const float* b_off_v  = (const float*)d_in[6];
    const float* w_mask_v = (const float*)d_in[7];
    const float* b_mask_v = (const float*)d_in[8];
    const float* w_h      = (const float*)d_in[9];
    const float* b_h      = (const float*)d_in[10];
    const float* w_v      = (const float*)d_in[11];
    const float* b_v      = (const float*)d_in[12];
    float* out = (float*)d_out;

    void *xn_p, *xh_p, *omh_p, *omv_p, *wB_p;
    cudaGetSymbolAddress(&xn_p,  g_x_nhwc);
    cudaGetSymbolAddress(&xh_p,  g_xh_nhwc);
    cudaGetSymbolAddress(&omh_p, g_omh);
    cudaGetSymbolAddress(&omv_p, g_omv);
    cudaGetSymbolAddress(&wB_p,  g_wB);
    const float* xn  = (const float*)xn_p;
    float*       xh  = (float*)xh_p;
    const float* omh = (const float*)omh_p;
    const float* omv = (const float*)omv_p;
    const float* wBh = (const float*)wB_p;
    const float* wBv = wBh + 12288;

    int smem_bytes = SMF_TOT * 4;   // 73216 B
    cudaFuncSetAttribute(pass_kernel<0,0>,
                         cudaFuncAttributeMaxDynamicSharedMemorySize, smem_bytes);
    cudaFuncSetAttribute(pass_kernel<1,1>,
                         cudaFuncAttributeMaxDynamicSharedMemorySize, smem_bytes);

    prep_weights<<<96, 256>>>(w_h, w_v);

    transpose_kernel<<<dim3(WW/32, HH, BB), dim3(32, 8)>>>(x);

    offmask_kernel<<<BB*HH/4, 256>>>(w_off_h, b_off_h, w_mask_h, b_mask_h,
                                     w_off_v, b_off_v, w_mask_v, b_mask_v);

    pass_kernel<0, 0><<<BB*HH, 192, smem_bytes>>>(xn, omh, wBh, b_h, xh);
    pass_kernel<1, 1><<<BB*HH, 192, smem_bytes>>>((const float*)xh, omv, wBv, b_v, out);
}

// round 15
// speedup vs baseline: 1.5597x; 1.5597x over previous
#include <cuda_runtime.h>
#include <math.h>
#include <stdint.h>

#define BB 8
#define CH 64
#define HH 128
#define WW 128

typedef unsigned long long u64;

// ---------------- scratch (device globals; no allocation allowed) ----------
__device__ float g_x_nhwc[BB*HH*WW*CH];   // x transposed to NHWC
__device__ float g_xh_nhwc[BB*HH*WW*CH];  // horizontal-pass output, NHWC
__device__ float g_omh[BB*HH*WW*12];      // dy0,dx0,dy1,dx1,dy2,dx2,m0,m1,m2,pad
__device__ float g_omv[BB*HH*WW*12];
// Packed weight images: [pass][k][c][64 floats]; row = 32 u64 out-pairs:
// u64 pos = i2*16 + og*2 + t holds (w[2jg], w[2jg+1]), jg = og*4 + i2*2 + t
__device__ __align__(16) float g_wB[2][12288];

// ---------------- f32x2 packed helpers (Blackwell FFMA2) -------------------
static __device__ __forceinline__ u64 pk2(float a, float b) {
    u64 r; asm("mov.b64 %0, {%1,%2};" : "=l"(r) : "f"(a), "f"(b)); return r;
}
static __device__ __forceinline__ void upk2(u64 v, float &a, float &b) {
    asm("mov.b64 {%0,%1}, %2;" : "=f"(a), "=f"(b) : "l"(v));
}
static __device__ __forceinline__ u64 ffma2(u64 a, u64 b, u64 c) {
    u64 d; asm("fma.rn.f32x2 %0, %1, %2, %3;" : "=l"(d) : "l"(a), "l"(b), "l"(c)); return d;
}
static __device__ __forceinline__ u64 fmul2(u64 a, u64 b) {
    u64 d; asm("mul.rn.f32x2 %0, %1, %2;" : "=l"(d) : "l"(a), "l"(b)); return d;
}
static __device__ __forceinline__ u64 fadd2(u64 a, u64 b) {
    u64 d; asm("add.rn.f32x2 %0, %1, %2;" : "=l"(d) : "l"(a), "l"(b)); return d;
}
static __device__ __forceinline__ float f4c(const float4 &v, int i) {
    return i == 0 ? v.x : (i == 1 ? v.y : (i == 2 ? v.z : v.w));
}

// ---------------- K-1: weight repack (runs once, tiny) ---------------------
__global__ __launch_bounds__(256) void prep_weights(
    const float* __restrict__ wh, const float* __restrict__ wv)
{
    int i = blockIdx.x*256 + threadIdx.x;
    if (i >= 24576) return;
    int pass = i / 12288;
    int r = i % 12288;
    int k = r / 4096;
    int rr = r % 4096;
    int c = rr / 64;
    int f = rr % 64;
    int pos = f >> 1, e = f & 1;
    int i2 = pos >> 4, og = (pos >> 1) & 7, t = pos & 1;
    int jg = og*4 + i2*2 + t;
    int o = 2*jg + e;
    const float* w = pass ? wv : wh;
    g_wB[pass][r] = w[o*192 + c*3 + k];
}

// ---------------- K0: NCHW -> NHWC transpose -------------------------------
__global__ __launch_bounds__(256) void transpose_kernel(const float* __restrict__ in) {
    __shared__ float tile[CH][33];
    int n = blockIdx.z, y = blockIdx.y, x0 = blockIdx.x * 32;
    int tx = threadIdx.x, ty = threadIdx.y;
    #pragma unroll
    for (int c = ty; c < CH; c += 8)
        tile[c][tx] = in[(((size_t)n*CH + c)*HH + y)*WW + x0 + tx];
    __syncthreads();
    int t = ty*32 + tx;
    #pragma unroll
    for (int i = 0; i < 8; i++) {
        int idx = t + i*256;
        int px = idx >> 6, c = idx & 63;
        g_x_nhwc[(((size_t)n*HH + y)*WW + x0 + px)*CH + c] = tile[c][px];
    }
}

// ---------------- K1: offsets + masks (warp-transposed gather) --------------
// Warp: cg = lane&3 (channel group), pxs = lane>>2 (8 pixels). Each thread
// accumulates 16 channels of one pixel-PAIR (rows y, y+1); 2-round shfl_xor
// over cg lanes completes the 64-channel sums. Warp-LDG touches 8 lines
// (8 wf) instead of 32.
__global__ __launch_bounds__(256, 2) void offmask_kernel(
    const float* __restrict__ woh, const float* __restrict__ boh,
    const float* __restrict__ wmh, const float* __restrict__ bmh,
    const float* __restrict__ wov, const float* __restrict__ bov,
    const float* __restrict__ wmv, const float* __restrict__ bmv)
{
    __shared__ float ws[64*6*12];
    int tid = threadIdx.x;
    for (int i = tid; i < 64*6*12; i += 256) {
        int o = i % 12, j = (i/12) % 6, c = i/72;
        float v = 0.f;
        if (o < 6)      v = (j < 3) ? woh[o*192 + c*3 + j] : wov[o*192 + c*3 + (j-3)];
        else if (o < 9) v = (j < 3) ? wmh[(o-6)*192 + c*3 + j] : wmv[(o-6)*192 + c*3 + (j-3)];
        ws[i] = v;
    }
    __syncthreads();

    int lane = tid & 31, wrp = tid >> 5;
    int cg = lane & 3;          // channel group: c in [r4*16 + cg*4, +4)
    int pxs = lane >> 2;        // 0..7

    int pairidx = blockIdx.x >> 1;              // 0..511
    int xhalf = (blockIdx.x & 1) * 64;
    int x = xhalf + wrp*8 + pxs;                // 0..127
    int row0 = pairidx*2;
    int y = row0 & 127;
    size_t p0 = (size_t)row0*WW + x;
    size_t p1 = p0 + WW;

    u64 H0a=0,H0b=0,H0c=0,H0d=0, V0a=0,V0b=0,V0c=0,V0d=0;
    u64 H1a=0,H1b=0,H1c=0,H1d=0, V1a=0,V1b=0,V1c=0,V1d=0;
    float H0e=0.f, V0e=0.f, H1e=0.f, V1e=0.f;

    const float* pc0 = g_x_nhwc + p0*CH;
    const float* pc1 = g_x_nhwc + p1*CH;
    bool hl = x > 0, hr = x < WW-1;
    bool vu = y > 0, vd = (y + 2) < HH;
    const float* pl0 = pc0 - CH;
    const float* pr0 = pc0 + CH;
    const float* pl1 = pc1 - CH;
    const float* pr1 = pc1 + CH;
    const float* pu  = pc0 - (size_t)WW*CH;
    const float* pd  = pc1 + (size_t)WW*CH;
    const float4 Z = make_float4(0.f,0.f,0.f,0.f);

    #pragma unroll
    for (int r4 = 0; r4 < 4; r4++) {
        int co = (r4*4 + cg)*4;                  // channel offset (floats)
        float4 fc0 = *(const float4*)(pc0 + co);
        float4 fc1 = *(const float4*)(pc1 + co);
        float4 fl0 = hl ? *(const float4*)(pl0 + co) : Z;
        float4 fr0 = hr ? *(const float4*)(pr0 + co) : Z;
        float4 fl1 = hl ? *(const float4*)(pl1 + co) : Z;
        float4 fr1 = hr ? *(const float4*)(pr1 + co) : Z;
        float4 fu  = vu ? *(const float4*)(pu  + co) : Z;
        float4 fd  = vd ? *(const float4*)(pd  + co) : Z;
        #pragma unroll
        for (int cc = 0; cc < 4; cc++) {
            int c = co + cc;                     // global channel 0..63
            float h0[3] = { f4c(fl0,cc), f4c(fc0,cc), f4c(fr0,cc) };
            float h1[3] = { f4c(fl1,cc), f4c(fc1,cc), f4c(fr1,cc) };
            float v0[3] = { f4c(fu,cc),  f4c(fc0,cc), f4c(fc1,cc) };
            float v1[3] = { f4c(fc0,cc), f4c(fc1,cc), f4c(fd,cc)  };
            #pragma unroll
            for (int j = 0; j < 3; j++) {
                const float* wb = &ws[(c*6 + j)*12];
                ulonglong2 W0 = *(const ulonglong2*)(wb);
                ulonglong2 W1 = *(const ulonglong2*)(wb + 4);
                float w8 = wb[8];
                u64 s0 = pk2(h0[j], h0[j]);
                H0a = ffma2(s0, W0.x, H0a); H0b = ffma2(s0, W0.y, H0b);
                H0c = ffma2(s0, W1.x, H0c); H0d = ffma2(s0, W1.y, H0d);
                H0e = fmaf(h0[j], w8, H0e);
                u64 s1 = pk2(h1[j], h1[j]);
                H1a = ffma2(s1, W0.x, H1a); H1b = ffma2(s1, W0.y, H1b);
                H1c = ffma2(s1, W1.x, H1c); H1d = ffma2(s1, W1.y, H1d);
                H1e = fmaf(h1[j], w8, H1e);

                const float* ub = &ws[(c*6 + j + 3)*12];
                ulonglong2 U0 = *(const ulonglong2*)(ub);
                ulonglong2 U1 = *(const ulonglong2*)(ub + 4);
                float u8 = ub[8];
                u64 t0 = pk2(v0[j], v0[j]);
                V0a = ffma2(t0, U0.x, V0a); V0b = ffma2(t0, U0.y, V0b);
                V0c = ffma2(t0, U1.x, V0c); V0d = ffma2(t0, U1.y, V0d);
                V0e = fmaf(v0[j], u8, V0e);
                u64 t1 = pk2(v1[j], v1[j]);
                V1a = ffma2(t1, U0.x, V1a); V1b = ffma2(t1, U0.y, V1b);
                V1c = ffma2(t1, U1.x, V1c); V1d = ffma2(t1, U1.y, V1d);
                V1e = fmaf(v1[j], u8, V1e);
            }
        }
    }

    // ---- reduce across the 4 cg lanes (same pxs) --------------------------
    #pragma unroll
    for (int m = 1; m <= 2; m <<= 1) {
        H0a = fadd2(H0a, __shfl_xor_sync(0xFFFFFFFFu, H0a, m));
        H0b = fadd2(H0b, __shfl_xor_sync(0xFFFFFFFFu, H0b, m));
        H0c = fadd2(H0c, __shfl_xor_sync(0xFFFFFFFFu, H0c, m));
        H0d = fadd2(H0d, __shfl_xor_sync(0xFFFFFFFFu, H0d, m));
        H1a = fadd2(H1a, __shfl_xor_sync(0xFFFFFFFFu, H1a, m));
        H1b = fadd2(H1b, __shfl_xor_sync(0xFFFFFFFFu, H1b, m));
        H1c = fadd2(H1c, __shfl_xor_sync(0xFFFFFFFFu, H1c, m));
        H1d = fadd2(H1d, __shfl_xor_sync(0xFFFFFFFFu, H1d, m));
        V0a = fadd2(V0a, __shfl_xor_sync(0xFFFFFFFFu, V0a, m));
        V0b = fadd2(V0b, __shfl_xor_sync(0xFFFFFFFFu, V0b, m));
        V0c = fadd2(V0c, __shfl_xor_sync(0xFFFFFFFFu, V0c, m));
        V0d = fadd2(V0d, __shfl_xor_sync(0xFFFFFFFFu, V0d, m));
        V1a = fadd2(V1a, __shfl_xor_sync(0xFFFFFFFFu, V1a, m));
        V1b = fadd2(V1b, __shfl_xor_sync(0xFFFFFFFFu, V1b, m));
        V1c = fadd2(V1c, __shfl_xor_sync(0xFFFFFFFFu, V1c, m));
        V1d = fadd2(V1d, __shfl_xor_sync(0xFFFFFFFFu, V1d, m));
        H0e += __shfl_xor_sync(0xFFFFFFFFu, H0e, m);
        H1e += __shfl_xor_sync(0xFFFFFFFFu, H1e, m);
        V0e += __shfl_xor_sync(0xFFFFFFFFu, V0e, m);
        V1e += __shfl_xor_sync(0xFFFFFFFFu, V1e, m);
    }

    if (cg == 0) {
        float b0 = __ldg(boh+0), b1 = __ldg(boh+1), b2 = __ldg(boh+2);
        float b3 = __ldg(boh+3), b4 = __ldg(boh+4), b5 = __ldg(boh+5);
        float c0 = __ldg(bov+0), c1 = __ldg(bov+1), c2 = __ldg(bov+2);
        float c3 = __ldg(bov+3), c4b = __ldg(bov+4), c5 = __ldg(bov+5);
        float mb0 = __ldg(bmh+0), mb1 = __ldg(bmh+1), mb2 = __ldg(bmh+2);
        float nb0 = __ldg(bmv+0), nb1 = __ldg(bmv+1), nb2 = __ldg(bmv+2);

        #pragma unroll
        for (int r = 0; r < 2; r++) {
            float A[9], V[9];
            if (r == 0) {
                upk2(H0a,A[0],A[1]); upk2(H0b,A[2],A[3]); upk2(H0c,A[4],A[5]);
                upk2(H0d,A[6],A[7]); A[8]=H0e;
                upk2(V0a,V[0],V[1]); upk2(V0b,V[2],V[3]); upk2(V0c,V[4],V[5]);
                upk2(V0d,V[6],V[7]); V[8]=V0e;
            } else {
                upk2(H1a,A[0],A[1]); upk2(H1b,A[2],A[3]); upk2(H1c,A[4],A[5]);
                upk2(H1d,A[6],A[7]); A[8]=H1e;
                upk2(V1a,V[0],V[1]); upk2(V1b,V[2],V[3]); upk2(V1c,V[4],V[5]);
                upk2(V1d,V[6],V[7]); V[8]=V1e;
            }
            size_t p = r ? p1 : p0;
            float mh0 = 1.f/(1.f + expf(-(A[6] + mb0)));
            float mh1 = 1.f/(1.f + expf(-(A[7] + mb1)));
            float mh2 = 1.f/(1.f + expf(-(A[8] + mb2)));
            float mv0 = 1.f/(1.f + expf(-(V[6] + nb0)));
            float mv1 = 1.f/(1.f + expf(-(V[7] + nb1)));
            float mv2 = 1.f/(1.f + expf(-(V[8] + nb2)));
            float* oh = g_omh + p*12;
            *(float4*)(oh+0) = make_float4(A[0]+b0, A[1]+b1, A[2]+b2, A[3]+b3);
            *(float4*)(oh+4) = make_float4(A[4]+b4, A[5]+b5, mh0, mh1);
            oh[8] = mh2;
            float* ov = g_omv + p*12;
            *(float4*)(ov+0) = make_float4(V[0]+c0, V[1]+c1, V[2]+c2, V[3]+c3);
            *(float4*)(ov+4) = make_float4(V[4]+c4b, V[5]+c5, mv0, mv1);
            ov[8] = mv2;
        }
    }
}

// ---------------- K2/K3: deformable axial pass (warp-specialized, R11) -----
// Block = 256 thr: threads 0-127 = producers (gather + B staging),
// threads 128-255 = consumers (GEMM, 8 px x 8 outs each).
// Double-buffered A (2x8192 f) and B (2x4096 f); one __syncthreads per tap.
// smem = 26496 floats = 105984 B -> 2 CTAs/SM.
#define SMF_B0  0
#define SMF_B1  4096
#define SMF_A0  8192
#define SMF_A1  16384
#define SMF_CW  24576
#define SMF_CB  26112
#define SMF_TOT 26496

template<int VERT, int OUT_NCHW>
__global__ __launch_bounds__(256, 2) void pass_kernel(
    const float* __restrict__ src,   // NHWC input
    const float* __restrict__ om,    // stride-12 offset/mask records
    const float* __restrict__ wB,    // packed weights [3][64][64]
    const float* __restrict__ bias,
    float* __restrict__ dst)
{
    extern __shared__ float smem[];
    float* Bbuf[2] = { smem + SMF_B0, smem + SMF_B1 };
    float* Abuf[2] = { smem + SMF_A0, smem + SMF_A1 };
    float* cww  = smem + SMF_CW;
    int*  cbase = (int*)(smem + SMF_CB);

    int tid = threadIdx.x;
    int row = blockIdx.x;            // n*H + y
    int n = row >> 7, y = row & 127;
    bool producer = tid < 128;

    // ---- prologue: corner weights/offsets (all threads) -------------------
    for (int t = tid; t < 384; t += 256) {
        int k = t >> 7, xp = t & 127;
        const float* omb = om + ((size_t)row*WW + xp)*12;
        float dyk = omb[2*k], dxk = omb[2*k + 1], mkk = omb[6 + k];
        float py = (float)y + dyk + (VERT ? (float)(k-1) : 0.f);
        float pxf = (float)xp + dxk + (VERT ? 0.f : (float)(k-1));
        float y0f = floorf(py), x0f = floorf(pxf);
        float wy = py - y0f, wx = pxf - x0f;
        int iy0 = (int)y0f, ix0 = (int)x0f;
        int iy1 = iy0 + 1,  ix1 = ix0 + 1;
        float vy0 = (iy0 >= 0 && iy0 < HH) ? 1.f : 0.f;
        float vy1 = (iy1 >= 0 && iy1 < HH) ? 1.f : 0.f;
        float vx0 = (ix0 >= 0 && ix0 < WW) ? 1.f : 0.f;
        float vx1 = (ix1 >= 0 && ix1 < WW) ? 1.f : 0.f;
        float* cw = &cww[(k*128 + xp)*4];
        cw[0] = (1.f-wy)*(1.f-wx)*vy0*vx0*mkk;
        cw[1] = (1.f-wy)*wx      *vy0*vx1*mkk;
        cw[2] = wy*(1.f-wx)      *vy1*vx0*mkk;
        cw[3] = wy*wx            *vy1*vx1*mkk;
        int cy0 = min(max(iy0,0),HH-1), cy1 = min(max(iy1,0),HH-1);
        int cx0 = min(max(ix0,0),WW-1), cx1 = min(max(ix1,0),WW-1);
        int b00 = ((n*HH + cy0)*WW + cx0)*CH;     // fits in 23 bits
        int fx = cx1 - cx0;
        int fy = cy1 - cy0;
        cbase[k*128 + xp] = b00 | (fx << 24) | (fy << 25);
    }
    // stage B(0) (all 256 threads)
    {
        const float4* s4 = (const float4*)wB;
        float4* d4 = (float4*)Bbuf[0];
        #pragma unroll
        for (int i = 0; i < 4; i++)
            d4[tid + i*256] = s4[tid + i*256];
    }
    __syncthreads();

    // producer roles
    int wid = tid >> 5, lane = tid & 31;
    int p8 = lane >> 3, c8l = lane & 7;
    // consumer roles
    int ctid = tid - 128;
    int og = ctid & 7, pgr = ctid >> 3;

    u64 acc[8][4];
    #pragma unroll
    for (int i = 0; i < 8; i++)
        #pragma unroll
        for (int j = 0; j < 4; j++) acc[i][j] = 0ull;

    // producers: gather tap 0 -> A0
    if (producer) {
        #pragma unroll
        for (int i = 0; i < 8; i++) {
            int pxg = wid*8 + i;
            int px = pxg*4 + p8;
            const float* cw = &cww[px*4];
            int cv = cbase[px];
            u64 w00p = pk2(cw[0], cw[0]);
            u64 w01p = pk2(cw[1], cw[1]);
            u64 w10p = pk2(cw[2], cw[2]);
            u64 w11p = pk2(cw[3], cw[3]);
            int b00 = cv & 0x00FFFFFF;
            int dx = ((cv >> 24) & 1) << 6;
            int dy = ((cv >> 25) & 1) << 13;
            int b01 = b00 + dx, b10 = b00 + dy, b11 = b10 + dx;
            #pragma unroll
            for (int h = 0; h < 2; h++) {
                int c4g = h*8 + c8l;
                int co = c4g*4;
                ulonglong2 q00 = *(const ulonglong2*)(src + b00 + co);
                ulonglong2 q01 = *(const ulonglong2*)(src + b01 + co);
                ulonglong2 q10 = *(const ulonglong2*)(src + b10 + co);
                ulonglong2 q11 = *(const ulonglong2*)(src + b11 + co);
                u64 r01 = ffma2(w00p, q00.x, ffma2(w01p, q01.x,
                          ffma2(w10p, q10.x, fmul2(w11p, q11.x))));
                u64 r23 = ffma2(w00p, q00.y, ffma2(w01p, q01.y,
                          ffma2(w10p, q10.y, fmul2(w11p, q11.y))));
                float r0, r1, r2, r3;
                upk2(r01, r0, r1); upk2(r23, r2, r3);
                int base = ((pxg ^ (c4g & 7)) << 2) + p8;
                float* ar = Abuf[0] + co*128 + base;
                ar[0*128] = r0; ar[1*128] = r1;
                ar[2*128] = r2; ar[3*128] = r3;
            }
        }
    }
    __syncthreads();

    // ---- pipelined taps: producers fill (k+1) while consumers GEMM (k) ----
    #pragma unroll
    for (int k = 0; k < 3; k++) {
        if (producer) {
            if (k < 2) {
                int kg = k + 1;
                int bsel = kg & 1;
                // stage B(kg)
                {
                    const float4* s4 = (const float4*)(wB + kg*4096);
                    float4* d4 = (float4*)Bbuf[bsel];
                    #pragma unroll
                    for (int i = 0; i < 8; i++)
                        d4[tid + i*128] = s4[tid + i*128];
                }
                // gather tap kg -> Abuf[bsel]
                #pragma unroll
                for (int i = 0; i < 8; i++) {
                    int pxg = wid*8 + i;
                    int px = pxg*4 + p8;
                    const float* cw = &cww[(kg*128 + px)*4];
                    int cv = cbase[kg*128 + px];
                    u64 w00p = pk2(cw[0], cw[0]);
                    u64 w01p = pk2(cw[1], cw[1]);
                    u64 w10p = pk2(cw[2], cw[2]);
                    u64 w11p = pk2(cw[3], cw[3]);
                    int b00 = cv & 0x00FFFFFF;
                    int dx = ((cv >> 24) & 1) << 6;
                    int dy = ((cv >> 25) & 1) << 13;
                    int b01 = b00 + dx, b10 = b00 + dy, b11 = b10 + dx;
                    #pragma unroll
                    for (int h = 0; h < 2; h++) {
                        int c4g = h*8 + c8l;
                        int co = c4g*4;
                        ulonglong2 q00 = *(const ulonglong2*)(src + b00 + co);
                        ulonglong2 q01 = *(const ulonglong2*)(src + b01 + co);
                        ulonglong2 q10 = *(const ulonglong2*)(src + b10 + co);
                        ulonglong2 q11 = *(const ulonglong2*)(src + b11 + co);
                        u64 r01 = ffma2(w00p, q00.x, ffma2(w01p, q01.x,
                                  ffma2(w10p, q10.x, fmul2(w11p, q11.x))));
                        u64 r23 = ffma2(w00p, q00.y, ffma2(w01p, q01.y,
                                  ffma2(w10p, q10.y, fmul2(w11p, q11.y))));
                        float r0, r1, r2, r3;
                        upk2(r01, r0, r1); upk2(r23, r2, r3);
                        int base = ((pxg ^ (c4g & 7)) << 2) + p8;
                        float* ar = Abuf[bsel] + co*128 + base;
                        ar[0*128] = r0; ar[1*128] = r1;
                        ar[2*128] = r2; ar[3*128] = r3;
                    }
                }
            }
        } else {
            // consumers: GEMM tap k
            const float* As = Abuf[k & 1];
            const float* Bs = Bbuf[k & 1];
            #pragma unroll 4
            for (int c = 0; c < 64; c++) {
                int s = (c >> 2) & 7;
                const float* arow = As + c*128;
                float4 a0 = *(const float4*)(arow + (((2*pgr)     ^ s) << 2));
                float4 a1 = *(const float4*)(arow + (((2*pgr + 1) ^ s) << 2));
                const float* brow = Bs + c*64;
                ulonglong2 bp0 = *(const ulonglong2*)(brow + og*4);
                ulonglong2 bp1 = *(const ulonglong2*)(brow + 32 + og*4);
                u64 W0 = bp0.x, W1 = bp0.y, W2 = bp1.x, W3 = bp1.y;
                #pragma unroll
                for (int i = 0; i < 8; i++) {
                    float av = (i < 4) ? f4c(a0, i) : f4c(a1, i - 4);
                    u64 ad = pk2(av, av);
                    acc[i][0] = ffma2(ad, W0, acc[i][0]);
                    acc[i][1] = ffma2(ad, W1, acc[i][1]);
                    acc[i][2] = ffma2(ad, W2, acc[i][2]);
                    acc[i][3] = ffma2(ad, W3, acc[i][3]);
                }
            }
        }
        __syncthreads();
    }

    // ---- epilogue: consumers add bias + store -----------------------------
    if (!producer) {
        float bv[8];
        #pragma unroll
        for (int m = 0; m < 8; m++) bv[m] = __ldg(bias + og*8 + m);

        if (OUT_NCHW) {
            #pragma unroll
            for (int m = 0; m < 8; m++) {
                int j = m >> 1, t = m & 1;
                float v[8];
                #pragma unroll
                for (int i = 0; i < 8; i++) {
                    float lo, hi; upk2(acc[i][j], lo, hi);
                    v[i] = (t ? hi : lo) + bv[m];
                }
                float* db = dst + (((size_t)(n*CH + og*8 + m))*HH + y)*WW + pgr*8;
                *(float4*)(db)     = make_float4(v[0], v[1], v[2], v[3]);
                *(float4*)(db + 4) = make_float4(v[4], v[5], v[6], v[7]);
            }
        } else {
            #pragma unroll
            for (int i = 0; i < 8; i++) {
                int px = pgr*8 + i;
                float s[8];
                #pragma unroll
                for (int j = 0; j < 4; j++) {
                    float lo, hi; upk2(acc[i][j], lo, hi);
                    s[2*j]   = lo + bv[2*j];
                    s[2*j+1] = hi + bv[2*j+1];
                }
                float* db = dst + ((size_t)row*WW + px)*CH + og*8;
                *(float4*)(db)     = make_float4(s[0], s[1], s[2], s[3]);
                *(float4*)(db + 4) = make_float4(s[4], s[5], s[6], s[7]);
            }
        }
    }
}

// ---------------- launch ---------------------------------------------------
extern "C" void kernel_launch(void* const* d_in, const int* in_sizes, int n_in,
                              void* d_out, int out_size) {
    const float* x        = (const float*)d_in[0];
    const float* w_off_h  = (const float*)d_in[1];
    const float* b_off_h  = (const float*)d_in[2];
    const float* w_mask_h = (const float*)d_in[3];
    const float* b_mask_h = (const float*)d_in[4];
    const float* w_off_v  = (const float*)d_in[5];
    const float* b_off_v  = (const float*)d_in[6];
    const float* w_mask_v = (const float*)d_in[7];
    const float* b_mask_v = (const float*)d_in[8];
    const float* w_h      = (const float*)d_in[9];
    const float* b_h      = (const float*)d_in[10];
    const float* w_v      = (const float*)d_in[11];
    const float* b_v      = (const float*)d_in[12];
    float* out = (float*)d_out;

    void *xn_p, *xh_p, *omh_p, *omv_p, *wB_p;
    cudaGetSymbolAddress(&xn_p,  g_x_nhwc);
    cudaGetSymbolAddress(&xh_p,  g_xh_nhwc);
    cudaGetSymbolAddress(&omh_p, g_omh);
    cudaGetSymbolAddress(&omv_p, g_omv);
    cudaGetSymbolAddress(&wB_p,  g_wB);
    const float* xn  = (const float*)xn_p;
    float*       xh  = (float*)xh_p;
    const float* omh = (const float*)omh_p;
    const float* omv = (const float*)omv_p;
    const float* wBh = (const float*)wB_p;
    const float* wBv = wBh + 12288;

    int smem_bytes = SMF_TOT * 4;   // 105984 B
    cudaFuncSetAttribute(pass_kernel<0,0>,
                         cudaFuncAttributeMaxDynamicSharedMemorySize, smem_bytes);
    cudaFuncSetAttribute(pass_kernel<1,1>,
                         cudaFuncAttributeMaxDynamicSharedMemorySize, smem_bytes);

    prep_weights<<<96, 256>>>(w_h, w_v);

    transpose_kernel<<<dim3(WW/32, HH, BB), dim3(32, 8)>>>(x);

    offmask_kernel<<<BB*HH, 256>>>(w_off_h, b_off_h, w_mask_h, b_mask_h,
                                   w_off_v, b_off_v, w_mask_v, b_mask_v);

    pass_kernel<0, 0><<<BB*HH, 256, smem_bytes>>>(xn, omh, wBh, b_h, xh);
    pass_kernel<1, 1><<<BB*HH, 256, smem_bytes>>>((const float*)xh, omv, wBv, b_v, out);
}

// round 16
// speedup vs baseline: 1.7749x; 1.1379x over previous
#include <cuda_runtime.h>
#include <math.h>
#include <stdint.h>

#define BB 8
#define CH 64
#define HH 128
#define WW 128

typedef unsigned long long u64;

// ---------------- scratch (device globals; no allocation allowed) ----------
__device__ float g_x_nhwc[BB*HH*WW*CH];   // x transposed to NHWC
__device__ float g_x_t[BB*HH*WW*CH];      // x transposed to N-W-H-C (y<->x)
__device__ float g_xh_nhwc[BB*HH*WW*CH];  // horizontal-pass output, NHWC
__device__ float g_omh[BB*HH*WW*12];      // dy0,dx0,dy1,dx1,dy2,dx2,m0,m1,m2,pad
__device__ float g_omv[BB*HH*WW*12];
// Packed weight images: [pass][k][c][64 floats]; row = 32 u64 out-pairs
__device__ __align__(16) float g_wB[2][12288];

// ---------------- f32x2 packed helpers (Blackwell FFMA2) -------------------
static __device__ __forceinline__ u64 pk2(float a, float b) {
    u64 r; asm("mov.b64 %0, {%1,%2};" : "=l"(r) : "f"(a), "f"(b)); return r;
}
static __device__ __forceinline__ void upk2(u64 v, float &a, float &b) {
    asm("mov.b64 {%0,%1}, %2;" : "=f"(a), "=f"(b) : "l"(v));
}
static __device__ __forceinline__ u64 ffma2(u64 a, u64 b, u64 c) {
    u64 d; asm("fma.rn.f32x2 %0, %1, %2, %3;" : "=l"(d) : "l"(a), "l"(b), "l"(c)); return d;
}
static __device__ __forceinline__ u64 fmul2(u64 a, u64 b) {
    u64 d; asm("mul.rn.f32x2 %0, %1, %2;" : "=l"(d) : "l"(a), "l"(b)); return d;
}
static __device__ __forceinline__ float f4c(const float4 &v, int i) {
    return i == 0 ? v.x : (i == 1 ? v.y : (i == 2 ? v.z : v.w));
}

// ---------------- K-1: weight repack (runs once, tiny) ---------------------
__global__ __launch_bounds__(256) void prep_weights(
    const float* __restrict__ wh, const float* __restrict__ wv)
{
    int i = blockIdx.x*256 + threadIdx.x;
    if (i >= 24576) return;
    int pass = i / 12288;
    int r = i % 12288;
    int k = r / 4096;
    int rr = r % 4096;
    int c = rr / 64;
    int f = rr % 64;
    int pos = f >> 1, e = f & 1;
    int i2 = pos >> 4, og = (pos >> 1) & 7, t = pos & 1;
    int jg = og*4 + i2*2 + t;
    int o = 2*jg + e;
    const float* w = pass ? wv : wh;
    g_wB[pass][r] = w[o*192 + c*3 + k];
}

// ---------------- K0: NCHW -> NHWC + N-W-H-C transposes --------------------
__global__ __launch_bounds__(256) void transpose_kernel(const float* __restrict__ in) {
    __shared__ float tile[CH][33];
    int n = blockIdx.z, y = blockIdx.y, x0 = blockIdx.x * 32;
    int tx = threadIdx.x, ty = threadIdx.y;
    #pragma unroll
    for (int c = ty; c < CH; c += 8)
        tile[c][tx] = in[(((size_t)n*CH + c)*HH + y)*WW + x0 + tx];
    __syncthreads();
    int t = ty*32 + tx;
    #pragma unroll
    for (int i = 0; i < 8; i++) {
        int idx = t + i*256;
        int px = idx >> 6, c = idx & 63;
        float v = tile[c][px];
        g_x_nhwc[(((size_t)n*HH + y)*WW + x0 + px)*CH + c] = v;
        g_x_t[(((size_t)n*WW + x0 + px)*HH + y)*CH + c] = v;
    }
}

// ---------------- K1: offsets + masks (one direction, staged rows) ----------
// Block = 2 "rows" of src (row = n*128 + r; 8192 floats each), 128 threads.
// Rows staged channel-major [c][132] (data at col px+1; cols 0,129 zero =
// conv padding). Thread = pixel px, accumulates both rows sharing weight
// broadcasts. TRANS selects output index mapping (v-direction uses g_x_t).
#define OM_ROW   (64*132)            // 8448 floats per staged row
#define OM_WS    (2*OM_ROW)          // weights offset
#define OM_TOT   (2*OM_ROW + 2304)   // 19200 floats = 76800 B

template<int TRANS>
__global__ __launch_bounds__(128, 2) void offmask_dir(
    const float* __restrict__ src,     // row-major rows of 8192 floats
    const float* __restrict__ woff, const float* __restrict__ boff,
    const float* __restrict__ wmask, const float* __restrict__ bmask,
    float* __restrict__ dst)           // stride-12 records
{
    extern __shared__ float smem[];
    float* A0 = smem;
    float* A1 = smem + OM_ROW;
    float* ws2 = smem + OM_WS;         // [c][j][12]: o0..5, m0..2, pad

    int tid = threadIdx.x;
    int r0 = blockIdx.x*2, r1 = r0 + 1;

    // weights -> smem
    for (int i = tid; i < 2304; i += 128) {
        int o = i % 12, j = (i/12) % 3, c = i/36;
        float v = 0.f;
        if (o < 6)      v = woff[o*192 + c*3 + j];
        else if (o < 9) v = wmask[(o-6)*192 + c*3 + j];
        ws2[i] = v;
    }
    // zero pad columns
    if (tid < 128) {
        int c = tid & 63;
        float* b = (tid >> 6) ? A1 : A0;
        b[c*132 + 0] = 0.f;
        b[c*132 + 129] = 0.f;
    }
    // stage 2 rows (coalesced float4 -> channel-major scatter)
    {
        const float4* s0 = (const float4*)(src + (size_t)r0*8192);
        const float4* s1 = (const float4*)(src + (size_t)r1*8192);
        for (int i = tid; i < 4096; i += 128) {
            int rsel = i >> 11, i2 = i & 2047;
            int px = i2 >> 4, c4 = i2 & 15;
            float4 v = rsel ? s1[i2] : s0[i2];
            float* b = (rsel ? A1 : A0) + (c4*4)*132 + 1 + px;
            b[0]     = v.x;
            b[132]   = v.y;
            b[264]   = v.z;
            b[396]   = v.w;
        }
    }
    __syncthreads();

    int px = tid;
    u64 H0a=0,H0b=0,H0c=0,H0d=0, H1a=0,H1b=0,H1c=0,H1d=0;
    float H0e=0.f, H1e=0.f;

    #pragma unroll 4
    for (int c = 0; c < 64; c++) {
        const float* a0 = A0 + c*132 + px;
        const float* a1 = A1 + c*132 + px;
        #pragma unroll
        for (int j = 0; j < 3; j++) {
            const float* wb = &ws2[(c*3 + j)*12];
            ulonglong2 W0 = *(const ulonglong2*)(wb);
            ulonglong2 W1 = *(const ulonglong2*)(wb + 4);
            float w8 = wb[8];
            float d0 = a0[j];
            float d1 = a1[j];
            u64 s0 = pk2(d0, d0);
            H0a = ffma2(s0, W0.x, H0a); H0b = ffma2(s0, W0.y, H0b);
            H0c = ffma2(s0, W1.x, H0c); H0d = ffma2(s0, W1.y, H0d);
            H0e = fmaf(d0, w8, H0e);
            u64 s1 = pk2(d1, d1);
            H1a = ffma2(s1, W0.x, H1a); H1b = ffma2(s1, W0.y, H1b);
            H1c = ffma2(s1, W1.x, H1c); H1d = ffma2(s1, W1.y, H1d);
            H1e = fmaf(d1, w8, H1e);
        }
    }

    float b0 = __ldg(boff+0), b1 = __ldg(boff+1), b2 = __ldg(boff+2);
    float b3 = __ldg(boff+3), b4 = __ldg(boff+4), b5 = __ldg(boff+5);
    float mb0 = __ldg(bmask+0), mb1 = __ldg(bmask+1), mb2 = __ldg(bmask+2);

    #pragma unroll
    for (int r = 0; r < 2; r++) {
        float A[9];
        if (r == 0) {
            upk2(H0a,A[0],A[1]); upk2(H0b,A[2],A[3]);
            upk2(H0c,A[4],A[5]); upk2(H0d,A[6],A[7]); A[8]=H0e;
        } else {
            upk2(H1a,A[0],A[1]); upk2(H1b,A[2],A[3]);
            upk2(H1c,A[4],A[5]); upk2(H1d,A[6],A[7]); A[8]=H1e;
        }
        int rr = r ? r1 : r0;
        size_t p;
        if (TRANS) {
            int n = rr >> 7, X = rr & 127;       // row = n*WW + X, pos = y
            p = ((size_t)(n*HH + px))*WW + X;
        } else {
            p = (size_t)rr*WW + px;              // row = n*HH + y
        }
        float m0 = 1.f/(1.f + expf(-(A[6] + mb0)));
        float m1 = 1.f/(1.f + expf(-(A[7] + mb1)));
        float m2 = 1.f/(1.f + expf(-(A[8] + mb2)));
        float* o = dst + p*12;
        *(float4*)(o+0) = make_float4(A[0]+b0, A[1]+b1, A[2]+b2, A[3]+b3);
        *(float4*)(o+4) = make_float4(A[4]+b4, A[5]+b5, m0, m1);
        o[8] = m2;
    }
}

// ---------------- K2/K3: deformable axial pass (warp-specialized, R11) -----
#define SMF_B0  0
#define SMF_B1  4096
#define SMF_A0  8192
#define SMF_A1  16384
#define SMF_CW  24576
#define SMF_CB  26112
#define SMF_TOT 26496

template<int VERT, int OUT_NCHW>
__global__ __launch_bounds__(256, 2) void pass_kernel(
    const float* __restrict__ src,   // NHWC input
    const float* __restrict__ om,    // stride-12 offset/mask records
    const float* __restrict__ wB,    // packed weights [3][64][64]
    const float* __restrict__ bias,
    float* __restrict__ dst)
{
    extern __shared__ float smem[];
    float* Bbuf[2] = { smem + SMF_B0, smem + SMF_B1 };
    float* Abuf[2] = { smem + SMF_A0, smem + SMF_A1 };
    float* cww  = smem + SMF_CW;
    int*  cbase = (int*)(smem + SMF_CB);

    int tid = threadIdx.x;
    int row = blockIdx.x;            // n*H + y
    int n = row >> 7, y = row & 127;
    bool producer = tid < 128;

    for (int t = tid; t < 384; t += 256) {
        int k = t >> 7, xp = t & 127;
        const float* omb = om + ((size_t)row*WW + xp)*12;
        float dyk = omb[2*k], dxk = omb[2*k + 1], mkk = omb[6 + k];
        float py = (float)y + dyk + (VERT ? (float)(k-1) : 0.f);
        float pxf = (float)xp + dxk + (VERT ? 0.f : (float)(k-1));
        float y0f = floorf(py), x0f = floorf(pxf);
        float wy = py - y0f, wx = pxf - x0f;
        int iy0 = (int)y0f, ix0 = (int)x0f;
        int iy1 = iy0 + 1,  ix1 = ix0 + 1;
        float vy0 = (iy0 >= 0 && iy0 < HH) ? 1.f : 0.f;
        float vy1 = (iy1 >= 0 && iy1 < HH) ? 1.f : 0.f;
        float vx0 = (ix0 >= 0 && ix0 < WW) ? 1.f : 0.f;
        float vx1 = (ix1 >= 0 && ix1 < WW) ? 1.f : 0.f;
        float* cw = &cww[(k*128 + xp)*4];
        cw[0] = (1.f-wy)*(1.f-wx)*vy0*vx0*mkk;
        cw[1] = (1.f-wy)*wx      *vy0*vx1*mkk;
        cw[2] = wy*(1.f-wx)      *vy1*vx0*mkk;
        cw[3] = wy*wx            *vy1*vx1*mkk;
        int cy0 = min(max(iy0,0),HH-1), cy1 = min(max(iy1,0),HH-1);
        int cx0 = min(max(ix0,0),WW-1), cx1 = min(max(ix1,0),WW-1);
        int b00 = ((n*HH + cy0)*WW + cx0)*CH;
        int fx = cx1 - cx0;
        int fy = cy1 - cy0;
        cbase[k*128 + xp] = b00 | (fx << 24) | (fy << 25);
    }
    {
        const float4* s4 = (const float4*)wB;
        float4* d4 = (float4*)Bbuf[0];
        #pragma unroll
        for (int i = 0; i < 4; i++)
            d4[tid + i*256] = s4[tid + i*256];
    }
    __syncthreads();

    int wid = tid >> 5, lane = tid & 31;
    int p8 = lane >> 3, c8l = lane & 7;
    int ctid = tid - 128;
    int og = ctid & 7, pgr = ctid >> 3;

    u64 acc[8][4];
    #pragma unroll
    for (int i = 0; i < 8; i++)
        #pragma unroll
        for (int j = 0; j < 4; j++) acc[i][j] = 0ull;

    if (producer) {
        #pragma unroll
        for (int i = 0; i < 8; i++) {
            int pxg = wid*8 + i;
            int px = pxg*4 + p8;
            const float* cw = &cww[px*4];
            int cv = cbase[px];
            u64 w00p = pk2(cw[0], cw[0]);
            u64 w01p = pk2(cw[1], cw[1]);
            u64 w10p = pk2(cw[2], cw[2]);
            u64 w11p = pk2(cw[3], cw[3]);
            int b00 = cv & 0x00FFFFFF;
            int dx = ((cv >> 24) & 1) << 6;
            int dy = ((cv >> 25) & 1) << 13;
            int b01 = b00 + dx, b10 = b00 + dy, b11 = b10 + dx;
            #pragma unroll
            for (int h = 0; h < 2; h++) {
                int c4g = h*8 + c8l;
                int co = c4g*4;
                ulonglong2 q00 = *(const ulonglong2*)(src + b00 + co);
                ulonglong2 q01 = *(const ulonglong2*)(src + b01 + co);
                ulonglong2 q10 = *(const ulonglong2*)(src + b10 + co);
                ulonglong2 q11 = *(const ulonglong2*)(src + b11 + co);
                u64 r01 = ffma2(w00p, q00.x, ffma2(w01p, q01.x,
                          ffma2(w10p, q10.x, fmul2(w11p, q11.x))));
                u64 r23 = ffma2(w00p, q00.y, ffma2(w01p, q01.y,
                          ffma2(w10p, q10.y, fmul2(w11p, q11.y))));
                float r0, r1, r2, r3;
                upk2(r01, r0, r1); upk2(r23, r2, r3);
                int base = ((pxg ^ (c4g & 7)) << 2) + p8;
                float* ar = Abuf[0] + co*128 + base;
                ar[0*128] = r0; ar[1*128] = r1;
                ar[2*128] = r2; ar[3*128] = r3;
            }
        }
    }
    __syncthreads();

    #pragma unroll
    for (int k = 0; k < 3; k++) {
        if (producer) {
            if (k < 2) {
                int kg = k + 1;
                int bsel = kg & 1;
                {
                    const float4* s4 = (const float4*)(wB + kg*4096);
                    float4* d4 = (float4*)Bbuf[bsel];
                    #pragma unroll
                    for (int i = 0; i < 8; i++)
                        d4[tid + i*128] = s4[tid + i*128];
                }
                #pragma unroll
                for (int i = 0; i < 8; i++) {
                    int pxg = wid*8 + i;
                    int px = pxg*4 + p8;
                    const float* cw = &cww[(kg*128 + px)*4];
                    int cv = cbase[kg*128 + px];
                    u64 w00p = pk2(cw[0], cw[0]);
                    u64 w01p = pk2(cw[1], cw[1]);
                    u64 w10p = pk2(cw[2], cw[2]);
                    u64 w11p = pk2(cw[3], cw[3]);
                    int b00 = cv & 0x00FFFFFF;
                    int dx = ((cv >> 24) & 1) << 6;
                    int dy = ((cv >> 25) & 1) << 13;
                    int b01 = b00 + dx, b10 = b00 + dy, b11 = b10 + dx;
                    #pragma unroll
                    for (int h = 0; h < 2; h++) {
                        int c4g = h*8 + c8l;
                        int co = c4g*4;
                        ulonglong2 q00 = *(const ulonglong2*)(src + b00 + co);
                        ulonglong2 q01 = *(const ulonglong2*)(src + b01 + co);
                        ulonglong2 q10 = *(const ulonglong2*)(src + b10 + co);
                        ulonglong2 q11 = *(const ulonglong2*)(src + b11 + co);
                        u64 r01 = ffma2(w00p, q00.x, ffma2(w01p, q01.x,
                                  ffma2(w10p, q10.x, fmul2(w11p, q11.x))));
                        u64 r23 = ffma2(w00p, q00.y, ffma2(w01p, q01.y,
                                  ffma2(w10p, q10.y, fmul2(w11p, q11.y))));
                        float r0, r1, r2, r3;
                        upk2(r01, r0, r1); upk2(r23, r2, r3);
                        int base = ((pxg ^ (c4g & 7)) << 2) + p8;
                        float* ar = Abuf[bsel] + co*128 + base;
                        ar[0*128] = r0; ar[1*128] = r1;
                        ar[2*128] = r2; ar[3*128] = r3;
                    }
                }
            }
        } else {
            const float* As = Abuf[k & 1];
            const float* Bs = Bbuf[k & 1];
            #pragma unroll 4
            for (int c = 0; c < 64; c++) {
                int s = (c >> 2) & 7;
                const float* arow = As + c*128;
                float4 a0 = *(const float4*)(arow + (((2*pgr)     ^ s) << 2));
                float4 a1 = *(const float4*)(arow + (((2*pgr + 1) ^ s) << 2));
                const float* brow = Bs + c*64;
                ulonglong2 bp0 = *(const ulonglong2*)(brow + og*4);
                ulonglong2 bp1 = *(const ulonglong2*)(brow + 32 + og*4);
                u64 W0 = bp0.x, W1 = bp0.y, W2 = bp1.x, W3 = bp1.y;
                #pragma unroll
                for (int i = 0; i < 8; i++) {
                    float av = (i < 4) ? f4c(a0, i) : f4c(a1, i - 4);
                    u64 ad = pk2(av, av);
                    acc[i][0] = ffma2(ad, W0, acc[i][0]);
                    acc[i][1] = ffma2(ad, W1, acc[i][1]);
                    acc[i][2] = ffma2(ad, W2, acc[i][2]);
                    acc[i][3] = ffma2(ad, W3, acc[i][3]);
                }
            }
        }
        __syncthreads();
    }

    if (!producer) {
        float bv[8];
        #pragma unroll
        for (int m = 0; m < 8; m++) bv[m] = __ldg(bias + og*8 + m);

        if (OUT_NCHW) {
            #pragma unroll
            for (int m = 0; m < 8; m++) {
                int j = m >> 1, t = m & 1;
                float v[8];
                #pragma unroll
                for (int i = 0; i < 8; i++) {
                    float lo, hi; upk2(acc[i][j], lo, hi);
                    v[i] = (t ? hi : lo) + bv[m];
                }
                float* db = dst + (((size_t)(n*CH + og*8 + m))*HH + y)*WW + pgr*8;
                *(float4*)(db)     = make_float4(v[0], v[1], v[2], v[3]);
                *(float4*)(db + 4) = make_float4(v[4], v[5], v[6], v[7]);
            }
        } else {
            #pragma unroll
            for (int i = 0; i < 8; i++) {
                int px = pgr*8 + i;
                float s[8];
                #pragma unroll
                for (int j = 0; j < 4; j++) {
                    float lo, hi; upk2(acc[i][j], lo, hi);
                    s[2*j]   = lo + bv[2*j];
                    s[2*j+1] = hi + bv[2*j+1];
                }
                float* db = dst + ((size_t)row*WW + px)*CH + og*8;
                *(float4*)(db)     = make_float4(s[0], s[1], s[2], s[3]);
                *(float4*)(db + 4) = make_float4(s[4], s[5], s[6], s[7]);
            }
        }
    }
}

// ---------------- launch ---------------------------------------------------
extern "C" void kernel_launch(void* const* d_in, const int* in_sizes, int n_in,
                              void* d_out, int out_size) {
    const float* x        = (const float*)d_in[0];
    const float* w_off_h  = (const float*)d_in[1];
    const float* b_off_h  = (const float*)d_in[2];
    const float* w_mask_h = (const float*)d_in[3];
    const float* b_mask_h = (const float*)d_in[4];
    const float* w_off_v  = (const float*)d_in[5];
    const float* b_off_v  = (const float*)d_in[6];
    const float* w_mask_v = (const float*)d_in[7];
    const float* b_mask_v = (const float*)d_in[8];
    const float* w_h      = (const float*)d_in[9];
    const float* b_h      = (const float*)d_in[10];
    const float* w_v      = (const float*)d_in[11];
    const float* b_v      = (const float*)d_in[12];
    float* out = (float*)d_out;

    void *xn_p, *xt_p, *xh_p, *omh_p, *omv_p, *wB_p;
    cudaGetSymbolAddress(&xn_p,  g_x_nhwc);
    cudaGetSymbolAddress(&xt_p,  g_x_t);
    cudaGetSymbolAddress(&xh_p,  g_xh_nhwc);
    cudaGetSymbolAddress(&omh_p, g_omh);
    cudaGetSymbolAddress(&omv_p, g_omv);
    cudaGetSymbolAddress(&wB_p,  g_wB);
    const float* xn  = (const float*)xn_p;
    const float* xt  = (const float*)xt_p;
    float*       xh  = (float*)xh_p;
    float*       omh = (float*)omh_p;
    float*       omv = (float*)omv_p;
    const float* wBh = (const float*)wB_p;
    const float* wBv = wBh + 12288;

    int smem_bytes = SMF_TOT * 4;   // 105984 B
    cudaFuncSetAttribute(pass_kernel<0,0>,
                         cudaFuncAttributeMaxDynamicSharedMemorySize, smem_bytes);
    cudaFuncSetAttribute(pass_kernel<1,1>,
                         cudaFuncAttributeMaxDynamicSharedMemorySize, smem_bytes);
    int om_smem = OM_TOT * 4;       // 76800 B
    cudaFuncSetAttribute(offmask_dir<0>,
                         cudaFuncAttributeMaxDynamicSharedMemorySize, om_smem);
    cudaFuncSetAttribute(offmask_dir<1>,
                         cudaFuncAttributeMaxDynamicSharedMemorySize, om_smem);

    prep_weights<<<96, 256>>>(w_h, w_v);

    transpose_kernel<<<dim3(WW/32, HH, BB), dim3(32, 8)>>>(x);

    offmask_dir<0><<<BB*HH/2, 128, om_smem>>>(xn, w_off_h, b_off_h,
                                              w_mask_h, b_mask_h, omh);
    offmask_dir<1><<<BB*WW/2, 128, om_smem>>>(xt, w_off_v, b_off_v,
                                              w_mask_v, b_mask_v, omv);

    pass_kernel<0, 0><<<BB*HH, 256, smem_bytes>>>(xn, omh, wBh, b_h, xh);
    pass_kernel<1, 1><<<BB*HH, 256, smem_bytes>>>((const float*)xh, omv, wBv, b_v, out);
}

// round 17
// speedup vs baseline: 2.0021x; 1.1280x over previous
#include <cuda_runtime.h>
#include <math.h>
#include <stdint.h>

#define BB 8
#define CH 64
#define HH 128
#define WW 128

typedef unsigned long long u64;

// ---------------- scratch (device globals; no allocation allowed) ----------
__device__ float g_x_nhwc[BB*HH*WW*CH];   // x transposed to NHWC
__device__ float g_xh_nhwc[BB*HH*WW*CH];  // horizontal-pass output, NHWC
__device__ float g_omh[BB*HH*WW*12];      // dy0,dx0,dy1,dx1,dy2,dx2,m0,m1,m2,pad
__device__ float g_omv[BB*HH*WW*12];
// Packed weight images: [pass][k][c][64 floats]; row = 32 u64 out-pairs
__device__ __align__(16) float g_wB[2][12288];

// ---------------- f32x2 packed helpers (Blackwell FFMA2) -------------------
static __device__ __forceinline__ u64 pk2(float a, float b) {
    u64 r; asm("mov.b64 %0, {%1,%2};" : "=l"(r) : "f"(a), "f"(b)); return r;
}
static __device__ __forceinline__ void upk2(u64 v, float &a, float &b) {
    asm("mov.b64 {%0,%1}, %2;" : "=f"(a), "=f"(b) : "l"(v));
}
static __device__ __forceinline__ u64 ffma2(u64 a, u64 b, u64 c) {
    u64 d; asm("fma.rn.f32x2 %0, %1, %2, %3;" : "=l"(d) : "l"(a), "l"(b), "l"(c)); return d;
}
static __device__ __forceinline__ u64 fmul2(u64 a, u64 b) {
    u64 d; asm("mul.rn.f32x2 %0, %1, %2;" : "=l"(d) : "l"(a), "l"(b)); return d;
}
static __device__ __forceinline__ float f4c(const float4 &v, int i) {
    return i == 0 ? v.x : (i == 1 ? v.y : (i == 2 ? v.z : v.w));
}

// ---------------- K-1: weight repack (runs once, tiny) ---------------------
__global__ __launch_bounds__(256) void prep_weights(
    const float* __restrict__ wh, const float* __restrict__ wv)
{
    int i = blockIdx.x*256 + threadIdx.x;
    if (i >= 24576) return;
    int pass = i / 12288;
    int r = i % 12288;
    int k = r / 4096;
    int rr = r % 4096;
    int c = rr / 64;
    int f = rr % 64;
    int pos = f >> 1, e = f & 1;
    int i2 = pos >> 4, og = (pos >> 1) & 7, t = pos & 1;
    int jg = og*4 + i2*2 + t;
    int o = 2*jg + e;
    const float* w = pass ? wv : wh;
    g_wB[pass][r] = w[o*192 + c*3 + k];
}

// ---------------- K0: NCHW -> NHWC transpose -------------------------------
__global__ __launch_bounds__(256) void transpose_kernel(const float* __restrict__ in) {
    __shared__ float tile[CH][33];
    int n = blockIdx.z, y = blockIdx.y, x0 = blockIdx.x * 32;
    int tx = threadIdx.x, ty = threadIdx.y;
    #pragma unroll
    for (int c = ty; c < CH; c += 8)
        tile[c][tx] = in[(((size_t)n*CH + c)*HH + y)*WW + x0 + tx];
    __syncthreads();
    int t = ty*32 + tx;
    #pragma unroll
    for (int i = 0; i < 8; i++) {
        int idx = t + i*256;
        int px = idx >> 6, c = idx & 63;
        g_x_nhwc[(((size_t)n*HH + y)*WW + x0 + px)*CH + c] = tile[c][px];
    }
}

// ---------------- K1: offsets + masks (NCHW-direct, coalesced) --------------
// Thread = pixel; loop over channels; all 5 neighbor loads are row-contiguous
// in NCHW -> fully coalesced. Both directions in one kernel share the center.
__global__ __launch_bounds__(256, 4) void offmask_kernel(
    const float* __restrict__ xin,
    const float* __restrict__ woh, const float* __restrict__ boh,
    const float* __restrict__ wmh, const float* __restrict__ bmh,
    const float* __restrict__ wov, const float* __restrict__ bov,
    const float* __restrict__ wmv, const float* __restrict__ bmv)
{
    __shared__ float ws[64*6*12];
    int tid = threadIdx.x;
    for (int i = tid; i < 64*6*12; i += 256) {
        int o = i % 12, j = (i/12) % 6, c = i/72;
        float v = 0.f;
        if (o < 6)      v = (j < 3) ? woh[o*192 + c*3 + j] : wov[o*192 + c*3 + (j-3)];
        else if (o < 9) v = (j < 3) ? wmh[(o-6)*192 + c*3 + j] : wmv[(o-6)*192 + c*3 + (j-3)];
        ws[i] = v;
    }
    __syncthreads();

    int x = tid & 127;
    int row = blockIdx.x*2 + (tid >> 7);     // n*HH + y
    int n = row >> 7, y = row & 127;
    bool hl = x > 0, hr = x < WW-1, vu = y > 0, vd = y < HH-1;

    const float* bp = xin + (((size_t)n*CH)*HH + y)*WW + x;

    u64 Ha=0,Hb=0,Hc=0,Hd=0, Va=0,Vb=0,Vc=0,Vd=0;
    float He=0.f, Ve=0.f;

    #pragma unroll 4
    for (int c = 0; c < 64; c++) {
        const float* pcb = bp + (size_t)c*(HH*WW);
        float ctr = pcb[0];
        float lft = hl ? pcb[-1]  : 0.f;
        float rgt = hr ? pcb[1]   : 0.f;
        float up  = vu ? pcb[-WW] : 0.f;
        float dwn = vd ? pcb[WW]  : 0.f;
        float hv[3] = { lft, ctr, rgt };
        float vv[3] = { up,  ctr, dwn };
        #pragma unroll
        for (int j = 0; j < 3; j++) {
            const float* wb = &ws[(c*6 + j)*12];
            ulonglong2 W0 = *(const ulonglong2*)(wb);
            ulonglong2 W1 = *(const ulonglong2*)(wb + 4);
            float w8 = wb[8];
            float h = hv[j];
            u64 s = pk2(h, h);
            Ha = ffma2(s, W0.x, Ha); Hb = ffma2(s, W0.y, Hb);
            Hc = ffma2(s, W1.x, Hc); Hd = ffma2(s, W1.y, Hd);
            He = fmaf(h, w8, He);

            const float* ub = &ws[(c*6 + j + 3)*12];
            ulonglong2 U0 = *(const ulonglong2*)(ub);
            ulonglong2 U1 = *(const ulonglong2*)(ub + 4);
            float u8 = ub[8];
            float v = vv[j];
            u64 t2 = pk2(v, v);
            Va = ffma2(t2, U0.x, Va); Vb = ffma2(t2, U0.y, Vb);
            Vc = ffma2(t2, U1.x, Vc); Vd = ffma2(t2, U1.y, Vd);
            Ve = fmaf(v, u8, Ve);
        }
    }

    float A[9], V[9];
    upk2(Ha,A[0],A[1]); upk2(Hb,A[2],A[3]);
    upk2(Hc,A[4],A[5]); upk2(Hd,A[6],A[7]); A[8]=He;
    upk2(Va,V[0],V[1]); upk2(Vb,V[2],V[3]);
    upk2(Vc,V[4],V[5]); upk2(Vd,V[6],V[7]); V[8]=Ve;

    size_t p = (size_t)row*WW + x;
    float mh0 = 1.f/(1.f + expf(-(A[6] + __ldg(bmh+0))));
    float mh1 = 1.f/(1.f + expf(-(A[7] + __ldg(bmh+1))));
    float mh2 = 1.f/(1.f + expf(-(A[8] + __ldg(bmh+2))));
    float mv0 = 1.f/(1.f + expf(-(V[6] + __ldg(bmv+0))));
    float mv1 = 1.f/(1.f + expf(-(V[7] + __ldg(bmv+1))));
    float mv2 = 1.f/(1.f + expf(-(V[8] + __ldg(bmv+2))));

    float* oh = g_omh + p*12;
    *(float4*)(oh+0) = make_float4(A[0]+__ldg(boh+0), A[1]+__ldg(boh+1),
                                   A[2]+__ldg(boh+2), A[3]+__ldg(boh+3));
    *(float4*)(oh+4) = make_float4(A[4]+__ldg(boh+4), A[5]+__ldg(boh+5), mh0, mh1);
    oh[8] = mh2;
    float* ov = g_omv + p*12;
    *(float4*)(ov+0) = make_float4(V[0]+__ldg(bov+0), V[1]+__ldg(bov+1),
                                   V[2]+__ldg(bov+2), V[3]+__ldg(bov+3));
    *(float4*)(ov+4) = make_float4(V[4]+__ldg(bov+4), V[5]+__ldg(bov+5), mv0, mv1);
    ov[8] = mv2;
}

// ---------------- K2/K3: deformable axial pass (warp-specialized, R11) -----
#define SMF_B0  0
#define SMF_B1  4096
#define SMF_A0  8192
#define SMF_A1  16384
#define SMF_CW  24576
#define SMF_CB  26112
#define SMF_TOT 26496

template<int VERT, int OUT_NCHW>
__global__ __launch_bounds__(256, 2) void pass_kernel(
    const float* __restrict__ src,   // NHWC input
    const float* __restrict__ om,    // stride-12 offset/mask records
    const float* __restrict__ wB,    // packed weights [3][64][64]
    const float* __restrict__ bias,
    float* __restrict__ dst)
{
    extern __shared__ float smem[];
    float* Bbuf[2] = { smem + SMF_B0, smem + SMF_B1 };
    float* Abuf[2] = { smem + SMF_A0, smem + SMF_A1 };
    float* cww  = smem + SMF_CW;
    int*  cbase = (int*)(smem + SMF_CB);

    int tid = threadIdx.x;
    int row = blockIdx.x;            // n*H + y
    int n = row >> 7, y = row & 127;
    bool producer = tid < 128;

    for (int t = tid; t < 384; t += 256) {
        int k = t >> 7, xp = t & 127;
        const float* omb = om + ((size_t)row*WW + xp)*12;
        float dyk = omb[2*k], dxk = omb[2*k + 1], mkk = omb[6 + k];
        float py = (float)y + dyk + (VERT ? (float)(k-1) : 0.f);
        float pxf = (float)xp + dxk + (VERT ? 0.f : (float)(k-1));
        float y0f = floorf(py), x0f = floorf(pxf);
        float wy = py - y0f, wx = pxf - x0f;
        int iy0 = (int)y0f, ix0 = (int)x0f;
        int iy1 = iy0 + 1,  ix1 = ix0 + 1;
        float vy0 = (iy0 >= 0 && iy0 < HH) ? 1.f : 0.f;
        float vy1 = (iy1 >= 0 && iy1 < HH) ? 1.f : 0.f;
        float vx0 = (ix0 >= 0 && ix0 < WW) ? 1.f : 0.f;
        float vx1 = (ix1 >= 0 && ix1 < WW) ? 1.f : 0.f;
        float* cw = &cww[(k*128 + xp)*4];
        cw[0] = (1.f-wy)*(1.f-wx)*vy0*vx0*mkk;
        cw[1] = (1.f-wy)*wx      *vy0*vx1*mkk;
        cw[2] = wy*(1.f-wx)      *vy1*vx0*mkk;
        cw[3] = wy*wx            *vy1*vx1*mkk;
        int cy0 = min(max(iy0,0),HH-1), cy1 = min(max(iy1,0),HH-1);
        int cx0 = min(max(ix0,0),WW-1), cx1 = min(max(ix1,0),WW-1);
        int b00 = ((n*HH + cy0)*WW + cx0)*CH;
        int fx = cx1 - cx0;
        int fy = cy1 - cy0;
        cbase[k*128 + xp] = b00 | (fx << 24) | (fy << 25);
    }
    {
        const float4* s4 = (const float4*)wB;
        float4* d4 = (float4*)Bbuf[0];
        #pragma unroll
        for (int i = 0; i < 4; i++)
            d4[tid + i*256] = s4[tid + i*256];
    }
    __syncthreads();

    int wid = tid >> 5, lane = tid & 31;
    int p8 = lane >> 3, c8l = lane & 7;
    int ctid = tid - 128;
    int og = ctid & 7, pgr = ctid >> 3;

    u64 acc[8][4];
    #pragma unroll
    for (int i = 0; i < 8; i++)
        #pragma unroll
        for (int j = 0; j < 4; j++) acc[i][j] = 0ull;

    if (producer) {
        #pragma unroll
        for (int i = 0; i < 8; i++) {
            int pxg = wid*8 + i;
            int px = pxg*4 + p8;
            const float* cw = &cww[px*4];
            int cv = cbase[px];
            u64 w00p = pk2(cw[0], cw[0]);
            u64 w01p = pk2(cw[1], cw[1]);
            u64 w10p = pk2(cw[2], cw[2]);
            u64 w11p = pk2(cw[3], cw[3]);
            int b00 = cv & 0x00FFFFFF;
            int dx = ((cv >> 24) & 1) << 6;
            int dy = ((cv >> 25) & 1) << 13;
            int b01 = b00 + dx, b10 = b00 + dy, b11 = b10 + dx;
            #pragma unroll
            for (int h = 0; h < 2; h++) {
                int c4g = h*8 + c8l;
                int co = c4g*4;
                ulonglong2 q00 = *(const ulonglong2*)(src + b00 + co);
                ulonglong2 q01 = *(const ulonglong2*)(src + b01 + co);
                ulonglong2 q10 = *(const ulonglong2*)(src + b10 + co);
                ulonglong2 q11 = *(const ulonglong2*)(src + b11 + co);
                u64 r01 = ffma2(w00p, q00.x, ffma2(w01p, q01.x,
                          ffma2(w10p, q10.x, fmul2(w11p, q11.x))));
                u64 r23 = ffma2(w00p, q00.y, ffma2(w01p, q01.y,
                          ffma2(w10p, q10.y, fmul2(w11p, q11.y))));
                float r0, r1, r2, r3;
                upk2(r01, r0, r1); upk2(r23, r2, r3);
                int base = ((pxg ^ (c4g & 7)) << 2) + p8;
                float* ar = Abuf[0] + co*128 + base;
                ar[0*128] = r0; ar[1*128] = r1;
                ar[2*128] = r2; ar[3*128] = r3;
            }
        }
    }
    __syncthreads();

    #pragma unroll
    for (int k = 0; k < 3; k++) {
        if (producer) {
            if (k < 2) {
                int kg = k + 1;
                int bsel = kg & 1;
                {
                    const float4* s4 = (const float4*)(wB + kg*4096);
                    float4* d4 = (float4*)Bbuf[bsel];
                    #pragma unroll
                    for (int i = 0; i < 8; i++)
                        d4[tid + i*128] = s4[tid + i*128];
                }
                #pragma unroll
                for (int i = 0; i < 8; i++) {
                    int pxg = wid*8 + i;
                    int px = pxg*4 + p8;
                    const float* cw = &cww[(kg*128 + px)*4];
                    int cv = cbase[kg*128 + px];
                    u64 w00p = pk2(cw[0], cw[0]);
                    u64 w01p = pk2(cw[1], cw[1]);
                    u64 w10p = pk2(cw[2], cw[2]);
                    u64 w11p = pk2(cw[3], cw[3]);
                    int b00 = cv & 0x00FFFFFF;
                    int dx = ((cv >> 24) & 1) << 6;
                    int dy = ((cv >> 25) & 1) << 13;
                    int b01 = b00 + dx, b10 = b00 + dy, b11 = b10 + dx;
                    #pragma unroll
                    for (int h = 0; h < 2; h++) {
                        int c4g = h*8 + c8l;
                        int co = c4g*4;
                        ulonglong2 q00 = *(const ulonglong2*)(src + b00 + co);
                        ulonglong2 q01 = *(const ulonglong2*)(src + b01 + co);
                        ulonglong2 q10 = *(const ulonglong2*)(src + b10 + co);
                        ulonglong2 q11 = *(const ulonglong2*)(src + b11 + co);
                        u64 r01 = ffma2(w00p, q00.x, ffma2(w01p, q01.x,
                                  ffma2(w10p, q10.x, fmul2(w11p, q11.x))));
                        u64 r23 = ffma2(w00p, q00.y, ffma2(w01p, q01.y,
                                  ffma2(w10p, q10.y, fmul2(w11p, q11.y))));
                        float r0, r1, r2, r3;
                        upk2(r01, r0, r1); upk2(r23, r2, r3);
                        int base = ((pxg ^ (c4g & 7)) << 2) + p8;
                        float* ar = Abuf[bsel] + co*128 + base;
                        ar[0*128] = r0; ar[1*128] = r1;
                        ar[2*128] = r2; ar[3*128] = r3;
                    }
                }
            }
        } else {
            const float* As = Abuf[k & 1];
            const float* Bs = Bbuf[k & 1];
            #pragma unroll 4
            for (int c = 0; c < 64; c++) {
                int s = (c >> 2) & 7;
                const float* arow = As + c*128;
                float4 a0 = *(const float4*)(arow + (((2*pgr)     ^ s) << 2));
                float4 a1 = *(const float4*)(arow + (((2*pgr + 1) ^ s) << 2));
                const float* brow = Bs + c*64;
                ulonglong2 bp0 = *(const ulonglong2*)(brow + og*4);
                ulonglong2 bp1 = *(const ulonglong2*)(brow + 32 + og*4);
                u64 W0 = bp0.x, W1 = bp0.y, W2 = bp1.x, W3 = bp1.y;
                #pragma unroll
                for (int i = 0; i < 8; i++) {
                    float av = (i < 4) ? f4c(a0, i) : f4c(a1, i - 4);
                    u64 ad = pk2(av, av);
                    acc[i][0] = ffma2(ad, W0, acc[i][0]);
                    acc[i][1] = ffma2(ad, W1, acc[i][1]);
                    acc[i][2] = ffma2(ad, W2, acc[i][2]);
                    acc[i][3] = ffma2(ad, W3, acc[i][3]);
                }
            }
        }
        __syncthreads();
    }

    if (!producer) {
        float bv[8];
        #pragma unroll
        for (int m = 0; m < 8; m++) bv[m] = __ldg(bias + og*8 + m);

        if (OUT_NCHW) {
            #pragma unroll
            for (int m = 0; m < 8; m++) {
                int j = m >> 1, t = m & 1;
                float v[8];
                #pragma unroll
                for (int i = 0; i < 8; i++) {
                    float lo, hi; upk2(acc[i][j], lo, hi);
                    v[i] = (t ? hi : lo) + bv[m];
                }
                float* db = dst + (((size_t)(n*CH + og*8 + m))*HH + y)*WW + pgr*8;
                *(float4*)(db)     = make_float4(v[0], v[1], v[2], v[3]);
                *(float4*)(db + 4) = make_float4(v[4], v[5], v[6], v[7]);
            }
        } else {
            #pragma unroll
            for (int i = 0; i < 8; i++) {
                int px = pgr*8 + i;
                float s[8];
                #pragma unroll
                for (int j = 0; j < 4; j++) {
                    float lo, hi; upk2(acc[i][j], lo, hi);
                    s[2*j]   = lo + bv[2*j];
                    s[2*j+1] = hi + bv[2*j+1];
                }
                float* db = dst + ((size_t)row*WW + px)*CH + og*8;
                *(float4*)(db)     = make_float4(s[0], s[1], s[2], s[3]);
                *(float4*)(db + 4) = make_float4(s[4], s[5], s[6], s[7]);
            }
        }
    }
}

// ---------------- launch ---------------------------------------------------
extern "C" void kernel_launch(void* const* d_in, const int* in_sizes, int n_in,
                              void* d_out, int out_size) {
    const float* x        = (const float*)d_in[0];
    const float* w_off_h  = (const float*)d_in[1];
    const float* b_off_h  = (const float*)d_in[2];
    const float* w_mask_h = (const float*)d_in[3];
    const float* b_mask_h = (const float*)d_in[4];
    const float* w_off_v  = (const float*)d_in[5];
    const float* b_off_v  = (const float*)d_in[6];
    const float* w_mask_v = (const float*)d_in[7];
    const float* b_mask_v = (const float*)d_in[8];
    const float* w_h      = (const float*)d_in[9];
    const float* b_h      = (const float*)d_in[10];
    const float* w_v      = (const float*)d_in[11];
    const float* b_v      = (const float*)d_in[12];
    float* out = (float*)d_out;

    void *xn_p, *xh_p, *omh_p, *omv_p, *wB_p;
    cudaGetSymbolAddress(&xn_p,  g_x_nhwc);
    cudaGetSymbolAddress(&xh_p,  g_xh_nhwc);
    cudaGetSymbolAddress(&omh_p, g_omh);
    cudaGetSymbolAddress(&omv_p, g_omv);
    cudaGetSymbolAddress(&wB_p,  g_wB);
    const float* xn  = (const float*)xn_p;
    float*       xh  = (float*)xh_p;
    const float* omh = (const float*)omh_p;
    const float* omv = (const float*)omv_p;
    const float* wBh = (const float*)wB_p;
    const float* wBv = wBh + 12288;

    int smem_bytes = SMF_TOT * 4;   // 105984 B
    cudaFuncSetAttribute(pass_kernel<0,0>,
                         cudaFuncAttributeMaxDynamicSharedMemorySize, smem_bytes);
    cudaFuncSetAttribute(pass_kernel<1,1>,
                         cudaFuncAttributeMaxDynamicSharedMemorySize, smem_bytes);

    prep_weights<<<96, 256>>>(w_h, w_v);

    transpose_kernel<<<dim3(WW/32, HH, BB), dim3(32, 8)>>>(x);

    offmask_kernel<<<BB*HH/2, 256>>>(x, w_off_h, b_off_h, w_mask_h, b_mask_h,
                                     w_off_v, b_off_v, w_mask_v, b_mask_v);

    pass_kernel<0, 0><<<BB*HH, 256, smem_bytes>>>(xn, omh, wBh, b_h, xh);
    pass_kernel<1, 1><<<BB*HH, 256, smem_bytes>>>((const float*)xh, omv, wBv, b_v, out);
}